// round 1
// baseline (speedup 1.0000x reference)
#include <cuda_runtime.h>
#include <cuda_bf16.h>

#define NBLOCKS 1184
#define NTHREADS 256
#define EPS 0.0001f

__device__ double g_partials[NBLOCKS];

__global__ __launch_bounds__(NTHREADS)
void gausscop_main(const float* __restrict__ pred_r,
                   const float* __restrict__ pred_params,
                   const float* __restrict__ pred_corr,
                   const float* __restrict__ y_true,
                   int n)
{
    float acc = 0.0f;
    const int stride = gridDim.x * blockDim.x;
    for (int i = blockIdx.x * blockDim.x + threadIdx.x; i < n; i += stride) {
        // ---- loads (coalesced, vectorized where alignment allows) ----
        float2 rr  = *(const float2*)(pred_r      + 2 * (long)i);
        float2 p01 = *(const float2*)(pred_params + 6 * (long)i);
        float2 p23 = *(const float2*)(pred_params + 6 * (long)i + 2);
        float2 p45 = *(const float2*)(pred_params + 6 * (long)i + 4);
        const float* pc = pred_corr + 3 * (long)i;
        float r12 = pc[0], r13 = pc[1], r23 = pc[2];
        float4 y = *(const float4*)(y_true + 4 * (long)i);

        float revert_f = y.x;
        int   revert_i = (int)y.x;
        float Rtop = y.y, Top = y.z, Close = y.w;

        // ---- means / sigmas: p = exp(pred_params) ----
        float u1 = __expf(p01.x), s1 = __expf(p01.y);
        float u2 = __expf(p23.x), s2 = __expf(p23.y);
        float u3 = __expf(p45.x), s3 = __expf(p45.y);

        float rs1 = 1.0f / fmaxf(s1, EPS);
        float rs2 = 1.0f / fmaxf(s2, EPS);
        float rs3 = 1.0f / fmaxf(s3, EPS);

        // t = (X - u)/s ; z = clamp(t, -3, 3) (exact simplification of
        // sqrt2*erfinv(2*clip(ndtr(t),eps,1-eps)-1) clipped to [-3,3])
        float t1 = (Rtop  - u1) * rs1;
        float t2 = (Top   - u2) * rs2;
        float t3 = (Close - u3) * rs3;
        float z1 = fminf(fmaxf(t1, -3.0f), 3.0f);
        float z2 = fminf(fmaxf(t2, -3.0f), 3.0f);
        float z3 = fminf(fmaxf(t3, -3.0f), 3.0f);

        // nll(u,s,x) = 0.5*((u-x)/max(s,eps))^2 + 0.5*log(s^2)
        //            = 0.5*t^2 + log(s) = 0.5*t^2 + param   (s = exp(param))
        float nll_sum = 0.5f * (t1 * t1 + t2 * t2 + t3 * t3)
                      + (p01.y + p23.y + p45.y);

        // ---- inverse correlation matrix ----
        float detR = 1.0f + 2.0f * r12 * r13 * r23
                   - r12 * r12 - r13 * r13 - r23 * r23;
        float inv_det = 1.0f / detR;
        float i00 = (1.0f - r23 * r23) * inv_det;
        float i01 = (r13 * r23 - r12) * inv_det;
        float i02 = (r12 * r23 - r13) * inv_det;
        float i11 = (1.0f - r13 * r13) * inv_det;
        float i12 = (r12 * r13 - r23) * inv_det;
        float i22 = (1.0f - r12 * r12) * inv_det;

        float exp_term = 0.5f * ((i00 - 1.0f) * z1 * z1
                               + (i11 - 1.0f) * z2 * z2
                               + (i22 - 1.0f) * z3 * z3)
                       + (i01 * z1 * z2 + i02 * z1 * z3 + i12 * z2 * z3);

        float c_gauss = 0.5f * __logf(fmaxf(detR, EPS)) + exp_term;
        float copula  = revert_f * (c_gauss + nll_sum);

        // ---- cross-entropy term: lse(pred_r) - pred_r[revert_i] ----
        float a = rr.x, b = rr.y;
        float m   = fmaxf(a, b);
        float lse = m + __logf(1.0f + __expf(-fabsf(a - b)));
        float sel = revert_i ? b : a;
        float ce  = lse - sel;

        acc += ce + copula;
    }

    // ---- warp reduce ----
    #pragma unroll
    for (int o = 16; o; o >>= 1)
        acc += __shfl_xor_sync(0xFFFFFFFFu, acc, o);

    __shared__ float warpsums[NTHREADS / 32];
    int lane = threadIdx.x & 31;
    int wid  = threadIdx.x >> 5;
    if (lane == 0) warpsums[wid] = acc;
    __syncthreads();

    if (threadIdx.x == 0) {
        double bs = 0.0;
        #pragma unroll
        for (int w = 0; w < NTHREADS / 32; w++) bs += (double)warpsums[w];
        g_partials[blockIdx.x] = bs;   // every block writes its slot: deterministic
    }
}

__global__ __launch_bounds__(256)
void gausscop_finalize(float* __restrict__ out, int n)
{
    __shared__ double sh[256];
    double s = 0.0;
    for (int i = threadIdx.x; i < NBLOCKS; i += 256) s += g_partials[i];
    sh[threadIdx.x] = s;
    __syncthreads();
    for (int stride = 128; stride > 0; stride >>= 1) {
        if (threadIdx.x < stride) sh[threadIdx.x] += sh[threadIdx.x + stride];
        __syncthreads();
    }
    if (threadIdx.x == 0)
        out[0] = (float)(sh[0] / (double)n);
}

extern "C" void kernel_launch(void* const* d_in, const int* in_sizes, int n_in,
                              void* d_out, int out_size)
{
    const float* pred_r      = (const float*)d_in[0];
    const float* pred_params = (const float*)d_in[1];
    const float* pred_corr   = (const float*)d_in[2];
    const float* y_true      = (const float*)d_in[3];
    int n = in_sizes[0] / 2;   // pred_r is (B, 2)

    gausscop_main<<<NBLOCKS, NTHREADS>>>(pred_r, pred_params, pred_corr, y_true, n);
    gausscop_finalize<<<1, 256>>>((float*)d_out, n);
}